// round 8
// baseline (speedup 1.0000x reference)
#include <cuda_runtime.h>
#include <math.h>

#define TPB 128
#define EPB 256   // elements per block: 2 per thread

typedef unsigned long long u64;

__device__ __forceinline__ u64 pk2(float x, float y) {
    u64 r; asm("mov.b64 %0, {%1,%2};" : "=l"(r) : "f"(x), "f"(y)); return r;
}
__device__ __forceinline__ void upk2(u64 v, float& x, float& y) {
    asm("mov.b64 {%0,%1}, %2;" : "=f"(x), "=f"(y) : "l"(v));
}
__device__ __forceinline__ u64 ffma2(u64 a, u64 b, u64 c) {
    u64 d; asm("fma.rn.f32x2 %0, %1, %2, %3;" : "=l"(d) : "l"(a), "l"(b), "l"(c)); return d;
}
__device__ __forceinline__ float gelu_f(float x) {
    return 0.5f * x * (1.0f + erff(x * 0.70710678118654752440f));
}

// FK for the 7-DOF Panda chain -> 7 keypoints
__device__ __forceinline__ void fk_eval(const float th[7], float kp[21]) {
    const float FR[7][9] = {
        {1,0,0,  0,1,0,   0,0,1},
        {1,0,0,  0,0,1,   0,-1,0},
        {1,0,0,  0,0,-1,  0,1,0},
        {1,0,0,  0,0,-1,  0,1,0},
        {1,0,0,  0,0,1,   0,-1,0},
        {1,0,0,  0,0,-1,  0,1,0},
        {1,0,0,  0,0,-1,  0,1,0}
    };
    const float FT[7][3] = {
        {0.f,0.f,0.333f},{0.f,0.f,0.f},{0.f,-0.316f,0.f},{0.0825f,0.f,0.f},
        {-0.0825f,0.384f,0.f},{0.f,0.f,0.f},{0.088f,0.f,0.f}
    };
    float r[9] = {1,0,0, 0,1,0, 0,0,1};
    float t[3] = {0,0,0};
    kp[0] = 0.f; kp[1] = 0.f; kp[2] = 0.f;
    int w = 3;
    #pragma unroll
    for (int i = 0; i < 7; i++) {
        float s, c; __sincosf(th[i], &s, &c);
        float sr[9];
        sr[0] =  FR[i][0]*c + FR[i][1]*s;  sr[1] = -FR[i][0]*s + FR[i][1]*c;  sr[2] = FR[i][2];
        sr[3] =  FR[i][3]*c + FR[i][4]*s;  sr[4] = -FR[i][3]*s + FR[i][4]*c;  sr[5] = FR[i][5];
        sr[6] =  FR[i][6]*c + FR[i][7]*s;  sr[7] = -FR[i][6]*s + FR[i][7]*c;  sr[8] = FR[i][8];
        float nt0 = r[0]*FT[i][0] + r[1]*FT[i][1] + r[2]*FT[i][2] + t[0];
        float nt1 = r[3]*FT[i][0] + r[4]*FT[i][1] + r[5]*FT[i][2] + t[1];
        float nt2 = r[6]*FT[i][0] + r[7]*FT[i][1] + r[8]*FT[i][2] + t[2];
        float nr[9];
        #pragma unroll
        for (int a = 0; a < 3; a++)
            #pragma unroll
            for (int bq = 0; bq < 3; bq++)
                nr[a*3+bq] = r[a*3+0]*sr[bq] + r[a*3+1]*sr[3+bq] + r[a*3+2]*sr[6+bq];
        #pragma unroll
        for (int q = 0; q < 9; q++) r[q] = nr[q];
        t[0] = nt0; t[1] = nt1; t[2] = nt2;
        if (i == 1 || i == 2 || i == 3 || i == 5 || i == 6) {
            kp[w] = t[0]; kp[w+1] = t[1]; kp[w+2] = t[2]; w += 3;
        }
    }
    kp[18] = t[0] + r[2]*0.107f;
    kp[19] = t[1] + r[5]*0.107f;
    kp[20] = t[2] + r[8]*0.107f;
}

// ---- smem float offsets ----
#define OFF_W1    0                    // 28*128 raw
#define OFF_GW2   3584                 // 128*128 (g1-scaled W2)
#define OFF_GW3   (OFF_GW2 + 16384)    // 128*8 (g2-scaled W3, padded)
#define OFF_B1    (OFF_GW3 + 1024)     // 128
#define OFF_G1    (OFF_B1 + 128)
#define OFF_BE1   (OFF_G1 + 128)
#define OFF_A2    (OFF_BE1 + 128)      // 128
#define OFF_CB2   (OFF_A2 + 128)       // 128
#define OFF_A3    (OFF_CB2 + 128)      // 8
#define OFF_CB3   (OFF_A3 + 8)         // 8
#define OFF_H     (OFF_CB3 + 8)        // fp32 staging as float2: 64 pairs * EPB
#define SMEM_BYTES ((OFF_H + 128 * EPB) * 4)

__global__ void __launch_bounds__(TPB, 1)
irm_kernel(const float* __restrict__ ang, const float* __restrict__ tgt,
           const float* __restrict__ Kc,  const float* __restrict__ Re,
           const float* __restrict__ te,  const int* __restrict__ vmk,
           const float* __restrict__ W1,  const float* __restrict__ b1,
           const float* __restrict__ g1,  const float* __restrict__ be1,
           const float* __restrict__ W2,  const float* __restrict__ b2,
           const float* __restrict__ g2,  const float* __restrict__ be2,
           const float* __restrict__ W3,  const float* __restrict__ b3,
           const float* __restrict__ slog, float* __restrict__ out, int Bn)
{
    extern __shared__ float sm[];
    float* sW1  = sm + OFF_W1;
    float* sGW2 = sm + OFF_GW2;
    float* sGW3 = sm + OFF_GW3;
    float* sb1  = sm + OFF_B1;
    float* sg1  = sm + OFF_G1;
    float* sbe1 = sm + OFF_BE1;
    float* sA2  = sm + OFF_A2;
    float* sCB2 = sm + OFF_CB2;
    float* sA3  = sm + OFF_A3;
    float* sCB3 = sm + OFF_CB3;
    float2* sH2 = (float2*)(sm + OFF_H);   // [64 pairs][EPB]

    const int tid = threadIdx.x;

    // ---- phase 1: raw weight loads + GW3 (g2-scaled W3) ----
    for (int i = tid; i < 3584;  i += TPB) sW1[i] = W1[i];
    for (int i = tid; i < 16384; i += TPB) sGW2[i] = W2[i];   // raw for now
    for (int i = tid; i < 1024;  i += TPB) {
        int k = i >> 3, j = i & 7;
        sGW3[i] = (j < 7) ? g2[k] * W3[k*7 + j] : 0.f;
    }
    if (tid < 128) {
        sb1[tid] = b1[tid]; sg1[tid] = g1[tid]; sbe1[tid] = be1[tid];
    }
    __syncthreads();

    // ---- phase 2: fold LN1 into layer-2 constants ----
    {
        float a2 = 0.f, cb2 = 0.f;
        for (int k = 0; k < 128; k++) {
            float w = sGW2[k*128 + tid];
            a2  += sg1[k]  * w;
            cb2 += sbe1[k] * w;
        }
        sA2[tid]  = a2;
        sCB2[tid] = cb2 + b2[tid];
    }
    if (tid < 8) {
        int c = tid;
        float a3 = 0.f, cb3 = 0.f;
        if (c < 7) {
            for (int k = 0; k < 128; k++) {
                a3  += sGW3[k*8 + c];
                cb3 += be2[k] * W3[k*7 + c];
            }
            cb3 += b3[c];
        }
        sA3[c]  = a3;
        sCB3[c] = cb3;
    }
    __syncthreads();

    // ---- phase 3: scale W2 in place by g1 ----
    for (int i = tid; i < 16384; i += TPB) sGW2[i] *= sg1[i >> 7];
    __syncthreads();

    // ---- two elements per thread ----
    const int b0r = blockIdx.x * EPB + tid;
    const int b1r = b0r + TPB;
    const bool v0 = (b0r < Bn), v1 = (b1r < Bn);
    const int be0 = v0 ? b0r : (Bn - 1);
    const int be1v = v1 ? b1r : (Bn - 1);

    float th0[7], th1[7];
    #pragma unroll
    for (int j = 0; j < 7; j++) { th0[j] = ang[(size_t)be0*7 + j]; th1[j] = ang[(size_t)be1v*7 + j]; }
    const float vm0 = (vmk[be0]  != 0) ? 1.f : 0.f;
    const float vm1 = (vmk[be1v] != 0) ? 1.f : 0.f;
    float ssv[3];
    #pragma unroll
    for (int j = 0; j < 3; j++) ssv[j] = 1.f / (1.f + expf(-slog[j]));

    const float LO[7] = {-2.8973f,-1.7628f,-2.8973f,-3.0718f,-2.8973f,-0.0175f,-2.8973f};
    const float HI[7] = { 2.8973f, 1.7628f, 2.8973f,-0.0698f, 2.8973f, 3.7525f, 2.8973f};

    float kp0[21], kp1[21];
    fk_eval(th0, kp0);
    fk_eval(th1, kp1);

    float* outA = out + (size_t)28 * Bn;   // all_angles (4,B,7)
    float* outK = out + (size_t)56 * Bn;   // all_kp     (4,B,7,3)

    if (v0) {
        #pragma unroll
        for (int j = 0; j < 7; j++)  outA[(size_t)be0*7 + j]  = th0[j];
        #pragma unroll
        for (int j = 0; j < 21; j++) outK[(size_t)be0*21 + j] = kp0[j];
    }
    if (v1) {
        #pragma unroll
        for (int j = 0; j < 7; j++)  outA[(size_t)be1v*7 + j]  = th1[j];
        #pragma unroll
        for (int j = 0; j < 21; j++) outK[(size_t)be1v*21 + j] = kp1[j];
    }

    for (int it = 0; it < 3; it++) {
        // ---- features for both elements (camera data from gmem, transient) ----
        float x0[28], x1[28];
        #pragma unroll 1
        for (int e = 0; e < 2; e++) {
            const int bb = e ? be1v : be0;
            const float vm = e ? vm1 : vm0;
            const float* kp = e ? kp1 : kp0;
            const float* th = e ? th1 : th0;
            float* x = e ? x1 : x0;
            float Rm[9], Km[6], tv[3];
            #pragma unroll
            for (int j = 0; j < 9; j++) Rm[j] = Re[(size_t)bb*9 + j];
            #pragma unroll
            for (int j = 0; j < 6; j++) Km[j] = Kc[(size_t)bb*9 + j];
            #pragma unroll
            for (int j = 0; j < 3; j++) tv[j] = te[(size_t)bb*3 + j];
            #pragma unroll
            for (int k = 0; k < 7; k++) {
                float px = kp[3*k], py = kp[3*k+1], pz = kp[3*k+2];
                float cx = Rm[0]*px + Rm[1]*py + Rm[2]*pz + tv[0];
                float cy = Rm[3]*px + Rm[4]*py + Rm[5]*pz + tv[1];
                float cz = Rm[6]*px + Rm[7]*py + Rm[8]*pz + tv[2];
                float z  = fmaxf(cz, 1e-6f);
                float inv = 1.0f / z;
                float nx = cx*inv, ny = cy*inv, nz = cz*inv;
                float u = Km[0]*nx + Km[1]*ny + Km[2]*nz;
                float v = Km[3]*nx + Km[4]*ny + Km[5]*nz;
                float dx = (tgt[(size_t)bb*14 + 2*k]   - u) * vm;
                float dy = (tgt[(size_t)bb*14 + 2*k+1] - v) * vm;
                x[2*k] = dx; x[2*k+1] = dy;
                x[21+k] = sqrtf(dx*dx + dy*dy);
            }
            #pragma unroll
            for (int j = 0; j < 7; j++) x[14+j] = th[j];
        }

        // ---- layer 1: 4 passes of 32 units, E=2 ----
        float sum1a = 0.f, sq1a = 0.f, sum1b = 0.f, sq1b = 0.f;
        #pragma unroll 1
        for (int p = 0; p < 4; p++) {
            u64 acc0[16], acc1[16];
            const u64* pb1 = (const u64*)sb1 + p*16;
            #pragma unroll
            for (int i = 0; i < 16; i++) { u64 bi = pb1[i]; acc0[i] = bi; acc1[i] = bi; }
            const float* wbase = sW1 + p*32;
            #pragma unroll 4
            for (int k = 0; k < 28; k++) {
                u64 xa = pk2(x0[k], x0[k]);
                u64 xb = pk2(x1[k], x1[k]);
                const ulonglong2* wrow = (const ulonglong2*)(wbase + k*128);
                #pragma unroll
                for (int i = 0; i < 8; i++) {
                    ulonglong2 w = wrow[i];
                    acc0[2*i]   = ffma2(xa, w.x, acc0[2*i]);
                    acc0[2*i+1] = ffma2(xa, w.y, acc0[2*i+1]);
                    acc1[2*i]   = ffma2(xb, w.x, acc1[2*i]);
                    acc1[2*i+1] = ffma2(xb, w.y, acc1[2*i+1]);
                }
            }
            #pragma unroll
            for (int i = 0; i < 16; i++) {
                float a0, a1; upk2(acc0[i], a0, a1);
                float h0 = gelu_f(a0), h1 = gelu_f(a1);
                sum1a += h0 + h1; sq1a += h0*h0 + h1*h1;
                sH2[(p*16 + i)*EPB + tid] = make_float2(h0, h1);
                float c0, c1; upk2(acc1[i], c0, c1);
                float g0 = gelu_f(c0), g1v = gelu_f(c1);
                sum1b += g0 + g1v; sq1b += g0*g0 + g1v*g1v;
                sH2[(p*16 + i)*EPB + tid + TPB] = make_float2(g0, g1v);
            }
        }
        float mu1a   = sum1a * (1.f/128.f);
        float rstd1a = rsqrtf(sq1a * (1.f/128.f) - mu1a*mu1a + 1e-5f);
        float m1a    = -mu1a * rstd1a;
        float mu1b   = sum1b * (1.f/128.f);
        float rstd1b = rsqrtf(sq1b * (1.f/128.f) - mu1b*mu1b + 1e-5f);
        float m1b    = -mu1b * rstd1b;

        // ---- layer 2: 4 passes of 32 units, E=2; LN1 folded ----
        float sum2a = 0.f, sq2a = 0.f, sum2b = 0.f, sq2b = 0.f;
        float S0[7] = {0,0,0,0,0,0,0};
        float S1[7] = {0,0,0,0,0,0,0};
        #pragma unroll 1
        for (int p = 0; p < 4; p++) {
            u64 acc0[16], acc1[16];
            #pragma unroll
            for (int i = 0; i < 16; i++) { acc0[i] = pk2(0.f,0.f); acc1[i] = pk2(0.f,0.f); }
            const float* wbase = sGW2 + p*32;
            #pragma unroll 2
            for (int j2 = 0; j2 < 64; j2++) {
                float2 ha = sH2[j2*EPB + tid];
                float2 hb = sH2[j2*EPB + tid + TPB];
                u64 a0 = pk2(ha.x, ha.x);
                u64 a1 = pk2(ha.y, ha.y);
                u64 bb0 = pk2(hb.x, hb.x);
                u64 bb1 = pk2(hb.y, hb.y);
                const ulonglong2* w0 = (const ulonglong2*)(wbase + (2*j2)*128);
                const ulonglong2* w1 = (const ulonglong2*)(wbase + (2*j2+1)*128);
                #pragma unroll
                for (int i = 0; i < 4; i++) {
                    ulonglong2 wa = w0[i];
                    acc0[2*i]   = ffma2(a0, wa.x, acc0[2*i]);
                    acc0[2*i+1] = ffma2(a0, wa.y, acc0[2*i+1]);
                    acc1[2*i]   = ffma2(bb0, wa.x, acc1[2*i]);
                    acc1[2*i+1] = ffma2(bb0, wa.y, acc1[2*i+1]);
                }
                #pragma unroll
                for (int i = 4; i < 8; i++) {
                    ulonglong2 wa = w0[i];
                    acc0[2*i]   = ffma2(a0, wa.x, acc0[2*i]);
                    acc0[2*i+1] = ffma2(a0, wa.y, acc0[2*i+1]);
                    acc1[2*i]   = ffma2(bb0, wa.x, acc1[2*i]);
                    acc1[2*i+1] = ffma2(bb0, wa.y, acc1[2*i+1]);
                }
                #pragma unroll
                for (int i = 0; i < 8; i++) {
                    ulonglong2 wb = w1[i];
                    acc0[2*i]   = ffma2(a1, wb.x, acc0[2*i]);
                    acc0[2*i+1] = ffma2(a1, wb.y, acc0[2*i+1]);
                    acc1[2*i]   = ffma2(bb1, wb.x, acc1[2*i]);
                    acc1[2*i+1] = ffma2(bb1, wb.y, acc1[2*i+1]);
                }
            }
            // epilogue: LN1 consts, gelu, stats, fused GEMM3 partials (weights shared E=2)
            #pragma unroll
            for (int i = 0; i < 16; i++) {
                int u = p*32 + 2*i;
                float2 a2 = *(const float2*)(sA2 + u);
                float2 cb = *(const float2*)(sCB2 + u);
                const float4* g0p = (const float4*)(sGW3 + u*8);
                const float4* g1p = (const float4*)(sGW3 + (u+1)*8);
                float4 ga = g0p[0], gb = g0p[1], gc = g1p[0], gd = g1p[1];

                float t0, t1; upk2(acc0[i], t0, t1);
                float pre0 = fmaf(rstd1a, t0, fmaf(m1a, a2.x, cb.x));
                float pre1 = fmaf(rstd1a, t1, fmaf(m1a, a2.y, cb.y));
                float h0 = gelu_f(pre0), h1 = gelu_f(pre1);
                sum2a += h0 + h1; sq2a += h0*h0 + h1*h1;
                S0[0] = fmaf(h0, ga.x, fmaf(h1, gc.x, S0[0]));
                S0[1] = fmaf(h0, ga.y, fmaf(h1, gc.y, S0[1]));
                S0[2] = fmaf(h0, ga.z, fmaf(h1, gc.z, S0[2]));
                S0[3] = fmaf(h0, ga.w, fmaf(h1, gc.w, S0[3]));
                S0[4] = fmaf(h0, gb.x, fmaf(h1, gd.x, S0[4]));
                S0[5] = fmaf(h0, gb.y, fmaf(h1, gd.y, S0[5]));
                S0[6] = fmaf(h0, gb.z, fmaf(h1, gd.z, S0[6]));

                float u0, u1v; upk2(acc1[i], u0, u1v);
                float qre0 = fmaf(rstd1b, u0, fmaf(m1b, a2.x, cb.x));
                float qre1 = fmaf(rstd1b, u1v, fmaf(m1b, a2.y, cb.y));
                float k0 = gelu_f(qre0), k1 = gelu_f(qre1);
                sum2b += k0 + k1; sq2b += k0*k0 + k1*k1;
                S1[0] = fmaf(k0, ga.x, fmaf(k1, gc.x, S1[0]));
                S1[1] = fmaf(k0, ga.y, fmaf(k1, gc.y, S1[1]));
                S1[2] = fmaf(k0, ga.z, fmaf(k1, gc.z, S1[2]));
                S1[3] = fmaf(k0, ga.w, fmaf(k1, gc.w, S1[3]));
                S1[4] = fmaf(k0, gb.x, fmaf(k1, gd.x, S1[4]));
                S1[5] = fmaf(k0, gb.y, fmaf(k1, gd.y, S1[5]));
                S1[6] = fmaf(k0, gb.z, fmaf(k1, gd.z, S1[6]));
            }
        }
        float mu2a   = sum2a * (1.f/128.f);
        float rstd2a = rsqrtf(sq2a * (1.f/128.f) - mu2a*mu2a + 1e-5f);
        float m2a    = -mu2a * rstd2a;
        float mu2b   = sum2b * (1.f/128.f);
        float rstd2b = rsqrtf(sq2b * (1.f/128.f) - mu2b*mu2b + 1e-5f);
        float m2b    = -mu2b * rstd2b;

        float ss = ssv[it];
        #pragma unroll
        for (int j = 0; j < 7; j++) {
            float d0 = fmaf(rstd2a, S0[j], fmaf(m2a, sA3[j], sCB3[j]));
            float n0 = th0[j] + ss * d0;
            th0[j] = fminf(fmaxf(n0, LO[j]), HI[j]);
            float d1 = fmaf(rstd2b, S1[j], fmaf(m2b, sA3[j], sCB3[j]));
            float n1 = th1[j] + ss * d1;
            th1[j] = fminf(fmaxf(n1, LO[j]), HI[j]);
        }
        fk_eval(th0, kp0);
        fk_eval(th1, kp1);

        const size_t w = (size_t)(it + 1);
        if (v0) {
            #pragma unroll
            for (int j = 0; j < 7; j++)  outA[w*(size_t)Bn*7  + (size_t)be0*7  + j] = th0[j];
            #pragma unroll
            for (int j = 0; j < 21; j++) outK[w*(size_t)Bn*21 + (size_t)be0*21 + j] = kp0[j];
        }
        if (v1) {
            #pragma unroll
            for (int j = 0; j < 7; j++)  outA[w*(size_t)Bn*7  + (size_t)be1v*7  + j] = th1[j];
            #pragma unroll
            for (int j = 0; j < 21; j++) outK[w*(size_t)Bn*21 + (size_t)be1v*21 + j] = kp1[j];
        }
    }

    if (v0) {
        #pragma unroll
        for (int j = 0; j < 7; j++)  out[(size_t)be0*7 + j] = th0[j];
        #pragma unroll
        for (int j = 0; j < 21; j++) out[(size_t)7*Bn + (size_t)be0*21 + j] = kp0[j];
    }
    if (v1) {
        #pragma unroll
        for (int j = 0; j < 7; j++)  out[(size_t)be1v*7 + j] = th1[j];
        #pragma unroll
        for (int j = 0; j < 21; j++) out[(size_t)7*Bn + (size_t)be1v*21 + j] = kp1[j];
    }
}

extern "C" void kernel_launch(void* const* d_in, const int* in_sizes, int n_in,
                              void* d_out, int out_size)
{
    const float* ang  = (const float*)d_in[0];
    const float* tgt  = (const float*)d_in[1];
    const float* Kc   = (const float*)d_in[2];
    const float* Re   = (const float*)d_in[4];
    const float* te   = (const float*)d_in[5];
    const int*   vmk  = (const int*)d_in[6];
    const float* W1   = (const float*)d_in[7];
    const float* b1   = (const float*)d_in[8];
    const float* g1   = (const float*)d_in[9];
    const float* be1  = (const float*)d_in[10];
    const float* W2   = (const float*)d_in[11];
    const float* b2   = (const float*)d_in[12];
    const float* g2   = (const float*)d_in[13];
    const float* be2  = (const float*)d_in[14];
    const float* W3   = (const float*)d_in[15];
    const float* b3   = (const float*)d_in[16];
    const float* slog = (const float*)d_in[17];

    const int Bn = in_sizes[0] / 7;
    const size_t smem = (size_t)SMEM_BYTES;

    cudaFuncSetAttribute(irm_kernel, cudaFuncAttributeMaxDynamicSharedMemorySize, (int)smem);

    const int grid = (Bn + EPB - 1) / EPB;
    irm_kernel<<<grid, TPB, smem>>>(ang, tgt, Kc, Re, te, vmk,
                                    W1, b1, g1, be1, W2, b2, g2, be2, W3, b3,
                                    slog, (float*)d_out, Bn);
}

// round 10
// speedup vs baseline: 1.1615x; 1.1615x over previous
#include <cuda_runtime.h>
#include <cuda_fp16.h>
#include <math.h>

#define TPB 256
#define EPB 512   // 2 elements per thread

typedef unsigned long long u64;

__device__ __forceinline__ u64 pk2(float x, float y) {
    u64 r; asm("mov.b64 %0, {%1,%2};" : "=l"(r) : "f"(x), "f"(y)); return r;
}
__device__ __forceinline__ void upk2(u64 v, float& x, float& y) {
    asm("mov.b64 {%0,%1}, %2;" : "=f"(x), "=f"(y) : "l"(v));
}
__device__ __forceinline__ u64 ffma2(u64 a, u64 b, u64 c) {
    u64 d; asm("fma.rn.f32x2 %0, %1, %2, %3;" : "=l"(d) : "l"(a), "l"(b), "l"(c)); return d;
}
__device__ __forceinline__ float gelu_f(float x) {
    return 0.5f * x * (1.0f + erff(x * 0.70710678118654752440f));
}
__device__ __forceinline__ unsigned h2_as_u32(__half2 h) {
    return *reinterpret_cast<unsigned*>(&h);
}
__device__ __forceinline__ __half2 u32_as_h2(unsigned u) {
    return *reinterpret_cast<__half2*>(&u);
}

// FK for the 7-DOF Panda chain -> 7 keypoints
__device__ __forceinline__ void fk_eval(const float th[7], float kp[21]) {
    const float FR[7][9] = {
        {1,0,0,  0,1,0,   0,0,1},
        {1,0,0,  0,0,1,   0,-1,0},
        {1,0,0,  0,0,-1,  0,1,0},
        {1,0,0,  0,0,-1,  0,1,0},
        {1,0,0,  0,0,1,   0,-1,0},
        {1,0,0,  0,0,-1,  0,1,0},
        {1,0,0,  0,0,-1,  0,1,0}
    };
    const float FT[7][3] = {
        {0.f,0.f,0.333f},{0.f,0.f,0.f},{0.f,-0.316f,0.f},{0.0825f,0.f,0.f},
        {-0.0825f,0.384f,0.f},{0.f,0.f,0.f},{0.088f,0.f,0.f}
    };
    float r[9] = {1,0,0, 0,1,0, 0,0,1};
    float t[3] = {0,0,0};
    kp[0] = 0.f; kp[1] = 0.f; kp[2] = 0.f;
    int w = 3;
    #pragma unroll
    for (int i = 0; i < 7; i++) {
        float s, c; __sincosf(th[i], &s, &c);
        float sr[9];
        sr[0] =  FR[i][0]*c + FR[i][1]*s;  sr[1] = -FR[i][0]*s + FR[i][1]*c;  sr[2] = FR[i][2];
        sr[3] =  FR[i][3]*c + FR[i][4]*s;  sr[4] = -FR[i][3]*s + FR[i][4]*c;  sr[5] = FR[i][5];
        sr[6] =  FR[i][6]*c + FR[i][7]*s;  sr[7] = -FR[i][6]*s + FR[i][7]*c;  sr[8] = FR[i][8];
        float nt0 = r[0]*FT[i][0] + r[1]*FT[i][1] + r[2]*FT[i][2] + t[0];
        float nt1 = r[3]*FT[i][0] + r[4]*FT[i][1] + r[5]*FT[i][2] + t[1];
        float nt2 = r[6]*FT[i][0] + r[7]*FT[i][1] + r[8]*FT[i][2] + t[2];
        float nr[9];
        #pragma unroll
        for (int a = 0; a < 3; a++)
            #pragma unroll
            for (int bq = 0; bq < 3; bq++)
                nr[a*3+bq] = r[a*3+0]*sr[bq] + r[a*3+1]*sr[3+bq] + r[a*3+2]*sr[6+bq];
        #pragma unroll
        for (int q = 0; q < 9; q++) r[q] = nr[q];
        t[0] = nt0; t[1] = nt1; t[2] = nt2;
        if (i == 1 || i == 2 || i == 3 || i == 5 || i == 6) {
            kp[w] = t[0]; kp[w+1] = t[1]; kp[w+2] = t[2]; w += 3;
        }
    }
    kp[18] = t[0] + r[2]*0.107f;
    kp[19] = t[1] + r[5]*0.107f;
    kp[20] = t[2] + r[8]*0.107f;
}

// ---- smem float offsets ----
#define OFF_W1    0                    // 28*128 raw
#define OFF_GW2   3584                 // 128*128 (g1-scaled W2)
#define OFF_GW3   (OFF_GW2 + 16384)    // 128*8 (g2-scaled W3, padded)
#define OFF_B1    (OFF_GW3 + 1024)     // 128
#define OFF_G1    (OFF_B1 + 128)
#define OFF_BE1   (OFF_G1 + 128)
#define OFF_A2    (OFF_BE1 + 128)      // 128
#define OFF_CB2   (OFF_A2 + 128)       // 128
#define OFF_A3    (OFF_CB2 + 128)      // 8
#define OFF_CB3   (OFF_A3 + 8)         // 8
#define OFF_H     (OFF_CB3 + 8)        // uint2 staging: 64 pairs * TPB * 8B
#define SMEM_BYTES (OFF_H * 4 + 64 * TPB * 8)

__global__ void __launch_bounds__(TPB, 1)
irm_kernel(const float* __restrict__ ang, const float* __restrict__ tgt,
           const float* __restrict__ Kc,  const float* __restrict__ Re,
           const float* __restrict__ te,  const int* __restrict__ vmk,
           const float* __restrict__ W1,  const float* __restrict__ b1,
           const float* __restrict__ g1,  const float* __restrict__ be1,
           const float* __restrict__ W2,  const float* __restrict__ b2,
           const float* __restrict__ g2,  const float* __restrict__ be2,
           const float* __restrict__ W3,  const float* __restrict__ b3,
           const float* __restrict__ slog, float* __restrict__ out, int Bn)
{
    extern __shared__ float sm[];
    float* sW1  = sm + OFF_W1;
    float* sGW2 = sm + OFF_GW2;
    float* sGW3 = sm + OFF_GW3;
    float* sb1  = sm + OFF_B1;
    float* sg1  = sm + OFF_G1;
    float* sbe1 = sm + OFF_BE1;
    float* sA2  = sm + OFF_A2;
    float* sCB2 = sm + OFF_CB2;
    float* sA3  = sm + OFF_A3;
    float* sCB3 = sm + OFF_CB3;
    uint2* sH   = (uint2*)(sm + OFF_H);   // [64 pairs][TPB], both elems packed

    const int tid = threadIdx.x;

    // ---- phase 1: raw weight loads + GW3 (g2-scaled W3) ----
    for (int i = tid; i < 3584;  i += TPB) sW1[i] = W1[i];
    for (int i = tid; i < 16384; i += TPB) sGW2[i] = W2[i];   // raw for now
    for (int i = tid; i < 1024;  i += TPB) {
        int k = i >> 3, j = i & 7;
        sGW3[i] = (j < 7) ? g2[k] * W3[k*7 + j] : 0.f;
    }
    if (tid < 128) {
        sb1[tid] = b1[tid]; sg1[tid] = g1[tid]; sbe1[tid] = be1[tid];
    }
    __syncthreads();

    // ---- phase 2: fold LN1 into layer-2 constants ----
    if (tid < 128) {
        float a2 = 0.f, cb2 = 0.f;
        for (int k = 0; k < 128; k++) {
            float w = sGW2[k*128 + tid];
            a2  += sg1[k]  * w;
            cb2 += sbe1[k] * w;
        }
        sA2[tid]  = a2;
        sCB2[tid] = cb2 + b2[tid];
    } else if (tid < 136) {
        int c = tid - 128;
        float a3 = 0.f, cb3 = 0.f;
        if (c < 7) {
            for (int k = 0; k < 128; k++) {
                a3  += sGW3[k*8 + c];
                cb3 += be2[k] * W3[k*7 + c];
            }
            cb3 += b3[c];
        }
        sA3[c]  = a3;
        sCB3[c] = cb3;
    }
    __syncthreads();

    // ---- phase 3: scale W2 in place by g1 ----
    for (int i = tid; i < 16384; i += TPB) sGW2[i] *= sg1[i >> 7];
    __syncthreads();

    // ---- two elements per thread ----
    const int b0r = blockIdx.x * EPB + tid;
    const int b1r = b0r + TPB;
    const bool v0 = (b0r < Bn), v1 = (b1r < Bn);
    const int be0  = v0 ? b0r : (Bn - 1);
    const int be1v = v1 ? b1r : (Bn - 1);

    float th0[7], th1[7];
    #pragma unroll
    for (int j = 0; j < 7; j++) { th0[j] = ang[(size_t)be0*7 + j]; th1[j] = ang[(size_t)be1v*7 + j]; }
    const float vm0 = (vmk[be0]  != 0) ? 1.f : 0.f;
    const float vm1 = (vmk[be1v] != 0) ? 1.f : 0.f;
    float ssv[3];
    #pragma unroll
    for (int j = 0; j < 3; j++) ssv[j] = 1.f / (1.f + expf(-slog[j]));

    const float LO[7] = {-2.8973f,-1.7628f,-2.8973f,-3.0718f,-2.8973f,-0.0175f,-2.8973f};
    const float HI[7] = { 2.8973f, 1.7628f, 2.8973f,-0.0698f, 2.8973f, 3.7525f, 2.8973f};

    float kp0[21], kp1[21];
    fk_eval(th0, kp0);
    fk_eval(th1, kp1);

    float* outA = out + (size_t)28 * Bn;   // all_angles (4,B,7)
    float* outK = out + (size_t)56 * Bn;   // all_kp     (4,B,7,3)

    if (v0) {
        #pragma unroll
        for (int j = 0; j < 7; j++)  outA[(size_t)be0*7 + j]  = th0[j];
        #pragma unroll
        for (int j = 0; j < 21; j++) outK[(size_t)be0*21 + j] = kp0[j];
    }
    if (v1) {
        #pragma unroll
        for (int j = 0; j < 7; j++)  outA[(size_t)be1v*7 + j]  = th1[j];
        #pragma unroll
        for (int j = 0; j < 21; j++) outK[(size_t)be1v*21 + j] = kp1[j];
    }

    for (int it = 0; it < 3; it++) {
        // ---- features for both elements (camera data from gmem, transient) ----
        float x0[28], x1[28];
        float mx0 = 0.f, mx1 = 0.f;
        #pragma unroll 1
        for (int e = 0; e < 2; e++) {
            const int bb = e ? be1v : be0;
            const float vm = e ? vm1 : vm0;
            const float* kp = e ? kp1 : kp0;
            const float* th = e ? th1 : th0;
            float* x = e ? x1 : x0;
            float Rm[9], Km[6], tv[3];
            #pragma unroll
            for (int j = 0; j < 9; j++) Rm[j] = Re[(size_t)bb*9 + j];
            #pragma unroll
            for (int j = 0; j < 6; j++) Km[j] = Kc[(size_t)bb*9 + j];
            #pragma unroll
            for (int j = 0; j < 3; j++) tv[j] = te[(size_t)bb*3 + j];
            float mx = 0.f;
            #pragma unroll
            for (int k = 0; k < 7; k++) {
                float px = kp[3*k], py = kp[3*k+1], pz = kp[3*k+2];
                float cx = Rm[0]*px + Rm[1]*py + Rm[2]*pz + tv[0];
                float cy = Rm[3]*px + Rm[4]*py + Rm[5]*pz + tv[1];
                float cz = Rm[6]*px + Rm[7]*py + Rm[8]*pz + tv[2];
                float z  = fmaxf(cz, 1e-6f);
                float inv = 1.0f / z;
                float nx = cx*inv, ny = cy*inv, nz = cz*inv;
                float u = Km[0]*nx + Km[1]*ny + Km[2]*nz;
                float v = Km[3]*nx + Km[4]*ny + Km[5]*nz;
                float dx = (tgt[(size_t)bb*14 + 2*k]   - u) * vm;
                float dy = (tgt[(size_t)bb*14 + 2*k+1] - v) * vm;
                x[2*k] = dx; x[2*k+1] = dy;
                float dm = sqrtf(dx*dx + dy*dy);
                x[21+k] = dm;
                mx = fmaxf(mx, dm);
            }
            #pragma unroll
            for (int j = 0; j < 7; j++) { x[14+j] = th[j]; mx = fmaxf(mx, fabsf(th[j])); }
            if (e) mx1 = mx; else mx0 = mx;
        }
        // per-element stage scales (LN is scale-invariant; keeps fp16 in range)
        const float s0 = 64.f / (1.f + mx0);
        const float s1 = 64.f / (1.f + mx1);

        // ---- layer 1: 4 passes of 32 units, E=2; stage scaled fp16 pairs ----
        float sum1a = 0.f, sq1a = 0.f, sum1b = 0.f, sq1b = 0.f;
        #pragma unroll 1
        for (int p = 0; p < 4; p++) {
            u64 acc0[16], acc1[16];
            const u64* pb1 = (const u64*)sb1 + p*16;
            #pragma unroll
            for (int i = 0; i < 16; i++) { u64 bi = pb1[i]; acc0[i] = bi; acc1[i] = bi; }
            const float* wbase = sW1 + p*32;
            #pragma unroll 4
            for (int k = 0; k < 28; k++) {
                u64 xa = pk2(x0[k], x0[k]);
                u64 xb = pk2(x1[k], x1[k]);
                const ulonglong2* wrow = (const ulonglong2*)(wbase + k*128);
                #pragma unroll
                for (int i = 0; i < 8; i++) {
                    ulonglong2 w = wrow[i];
                    acc0[2*i]   = ffma2(xa, w.x, acc0[2*i]);
                    acc0[2*i+1] = ffma2(xa, w.y, acc0[2*i+1]);
                    acc1[2*i]   = ffma2(xb, w.x, acc1[2*i]);
                    acc1[2*i+1] = ffma2(xb, w.y, acc1[2*i+1]);
                }
            }
            #pragma unroll
            for (int i = 0; i < 16; i++) {
                float a0, a1; upk2(acc0[i], a0, a1);
                __half2 h2a = __float22half2_rn(make_float2(gelu_f(a0)*s0, gelu_f(a1)*s0));
                float2 ra = __half22float2(h2a);            // rounded values for stats
                sum1a += ra.x + ra.y; sq1a += ra.x*ra.x + ra.y*ra.y;
                float c0, c1; upk2(acc1[i], c0, c1);
                __half2 h2b = __float22half2_rn(make_float2(gelu_f(c0)*s1, gelu_f(c1)*s1));
                float2 rb = __half22float2(h2b);
                sum1b += rb.x + rb.y; sq1b += rb.x*rb.x + rb.y*rb.y;
                sH[(p*16 + i)*TPB + tid] = make_uint2(h2_as_u32(h2a), h2_as_u32(h2b));
            }
        }
        float mu1a = sum1a * (1.f/128.f);
        float mu1b = sum1b * (1.f/128.f);
        // eps correction for scaled staging: rstd_eff = 1/sqrt(var_s + eps*s^2)
        float rstd1a = rsqrtf(sq1a*(1.f/128.f) - mu1a*mu1a + 1e-5f*s0*s0);
        float m1a    = -mu1a * rstd1a;
        float rstd1b = rsqrtf(sq1b*(1.f/128.f) - mu1b*mu1b + 1e-5f*s1*s1);
        float m1b    = -mu1b * rstd1b;

        // ---- layer 2: 4 passes of 32 units, E=2; LN1 folded ----
        float sum2a = 0.f, sq2a = 0.f, sum2b = 0.f, sq2b = 0.f;
        float S0[7] = {0,0,0,0,0,0,0};
        float S1[7] = {0,0,0,0,0,0,0};
        #pragma unroll 1
        for (int p = 0; p < 4; p++) {
            u64 acc0[16], acc1[16];
            #pragma unroll
            for (int i = 0; i < 16; i++) { acc0[i] = pk2(0.f,0.f); acc1[i] = pk2(0.f,0.f); }
            const float* wbase = sGW2 + p*32;
            #pragma unroll 2
            for (int j2 = 0; j2 < 64; j2++) {
                uint2 hw = sH[j2*TPB + tid];
                float2 fa = __half22float2(u32_as_h2(hw.x));
                float2 fb = __half22float2(u32_as_h2(hw.y));
                u64 a0 = pk2(fa.x, fa.x);
                u64 a1 = pk2(fa.y, fa.y);
                u64 bb0 = pk2(fb.x, fb.x);
                u64 bb1 = pk2(fb.y, fb.y);
                const ulonglong2* w0 = (const ulonglong2*)(wbase + (2*j2)*128);
                const ulonglong2* w1 = (const ulonglong2*)(wbase + (2*j2+1)*128);
                #pragma unroll
                for (int i = 0; i < 8; i++) {
                    ulonglong2 wa = w0[i];
                    acc0[2*i]   = ffma2(a0, wa.x, acc0[2*i]);
                    acc0[2*i+1] = ffma2(a0, wa.y, acc0[2*i+1]);
                    acc1[2*i]   = ffma2(bb0, wa.x, acc1[2*i]);
                    acc1[2*i+1] = ffma2(bb0, wa.y, acc1[2*i+1]);
                }
                #pragma unroll
                for (int i = 0; i < 8; i++) {
                    ulonglong2 wb = w1[i];
                    acc0[2*i]   = ffma2(a1, wb.x, acc0[2*i]);
                    acc0[2*i+1] = ffma2(a1, wb.y, acc0[2*i+1]);
                    acc1[2*i]   = ffma2(bb1, wb.x, acc1[2*i]);
                    acc1[2*i+1] = ffma2(bb1, wb.y, acc1[2*i+1]);
                }
            }
            // epilogue: LN1 consts, gelu, stats, fused GEMM3 partials
            #pragma unroll
            for (int i = 0; i < 16; i++) {
                int u = p*32 + 2*i;
                float2 a2 = *(const float2*)(sA2 + u);
                float2 cb = *(const float2*)(sCB2 + u);
                const float4* g0p = (const float4*)(sGW3 + u*8);
                const float4* g1p = (const float4*)(sGW3 + (u+1)*8);
                float4 ga = g0p[0], gb = g0p[1], gc = g1p[0], gd = g1p[1];

                float t0, t1; upk2(acc0[i], t0, t1);
                float pre0 = fmaf(rstd1a, t0, fmaf(m1a, a2.x, cb.x));
                float pre1 = fmaf(rstd1a, t1, fmaf(m1a, a2.y, cb.y));
                float h0 = gelu_f(pre0), h1 = gelu_f(pre1);
                sum2a += h0 + h1; sq2a += h0*h0 + h1*h1;
                S0[0] = fmaf(h0, ga.x, fmaf(h1, gc.x, S0[0]));
                S0[1] = fmaf(h0, ga.y, fmaf(h1, gc.y, S0[1]));
                S0[2] = fmaf(h0, ga.z, fmaf(h1, gc.z, S0[2]));
                S0[3] = fmaf(h0, ga.w, fmaf(h1, gc.w, S0[3]));
                S0[4] = fmaf(h0, gb.x, fmaf(h1, gd.x, S0[4]));
                S0[5] = fmaf(h0, gb.y, fmaf(h1, gd.y, S0[5]));
                S0[6] = fmaf(h0, gb.z, fmaf(h1, gd.z, S0[6]));

                float u0, u1v; upk2(acc1[i], u0, u1v);
                float q0 = fmaf(rstd1b, u0, fmaf(m1b, a2.x, cb.x));
                float q1 = fmaf(rstd1b, u1v, fmaf(m1b, a2.y, cb.y));
                float k0 = gelu_f(q0), k1 = gelu_f(q1);
                sum2b += k0 + k1; sq2b += k0*k0 + k1*k1;
                S1[0] = fmaf(k0, ga.x, fmaf(k1, gc.x, S1[0]));
                S1[1] = fmaf(k0, ga.y, fmaf(k1, gc.y, S1[1]));
                S1[2] = fmaf(k0, ga.z, fmaf(k1, gc.z, S1[2]));
                S1[3] = fmaf(k0, ga.w, fmaf(k1, gc.w, S1[3]));
                S1[4] = fmaf(k0, gb.x, fmaf(k1, gd.x, S1[4]));
                S1[5] = fmaf(k0, gb.y, fmaf(k1, gd.y, S1[5]));
                S1[6] = fmaf(k0, gb.z, fmaf(k1, gd.z, S1[6]));
            }
        }
        float mu2a   = sum2a * (1.f/128.f);
        float rstd2a = rsqrtf(sq2a * (1.f/128.f) - mu2a*mu2a + 1e-5f);
        float m2a    = -mu2a * rstd2a;
        float mu2b   = sum2b * (1.f/128.f);
        float rstd2b = rsqrtf(sq2b * (1.f/128.f) - mu2b*mu2b + 1e-5f);
        float m2b    = -mu2b * rstd2b;

        float ss = ssv[it];
        #pragma unroll
        for (int j = 0; j < 7; j++) {
            float d0 = fmaf(rstd2a, S0[j], fmaf(m2a, sA3[j], sCB3[j]));
            float n0 = th0[j] + ss * d0;
            th0[j] = fminf(fmaxf(n0, LO[j]), HI[j]);
            float d1 = fmaf(rstd2b, S1[j], fmaf(m2b, sA3[j], sCB3[j]));
            float n1 = th1[j] + ss * d1;
            th1[j] = fminf(fmaxf(n1, LO[j]), HI[j]);
        }
        fk_eval(th0, kp0);
        fk_eval(th1, kp1);

        const size_t w = (size_t)(it + 1);
        if (v0) {
            #pragma unroll
            for (int j = 0; j < 7; j++)  outA[w*(size_t)Bn*7  + (size_t)be0*7  + j] = th0[j];
            #pragma unroll
            for (int j = 0; j < 21; j++) outK[w*(size_t)Bn*21 + (size_t)be0*21 + j] = kp0[j];
        }
        if (v1) {
            #pragma unroll
            for (int j = 0; j < 7; j++)  outA[w*(size_t)Bn*7  + (size_t)be1v*7  + j] = th1[j];
            #pragma unroll
            for (int j = 0; j < 21; j++) outK[w*(size_t)Bn*21 + (size_t)be1v*21 + j] = kp1[j];
        }
    }

    if (v0) {
        #pragma unroll
        for (int j = 0; j < 7; j++)  out[(size_t)be0*7 + j] = th0[j];
        #pragma unroll
        for (int j = 0; j < 21; j++) out[(size_t)7*Bn + (size_t)be0*21 + j] = kp0[j];
    }
    if (v1) {
        #pragma unroll
        for (int j = 0; j < 7; j++)  out[(size_t)be1v*7 + j] = th1[j];
        #pragma unroll
        for (int j = 0; j < 21; j++) out[(size_t)7*Bn + (size_t)be1v*21 + j] = kp1[j];
    }
}

extern "C" void kernel_launch(void* const* d_in, const int* in_sizes, int n_in,
                              void* d_out, int out_size)
{
    const float* ang  = (const float*)d_in[0];
    const float* tgt  = (const float*)d_in[1];
    const float* Kc   = (const float*)d_in[2];
    const float* Re   = (const float*)d_in[4];
    const float* te   = (const float*)d_in[5];
    const int*   vmk  = (const int*)d_in[6];
    const float* W1   = (const float*)d_in[7];
    const float* b1   = (const float*)d_in[8];
    const float* g1   = (const float*)d_in[9];
    const float* be1  = (const float*)d_in[10];
    const float* W2   = (const float*)d_in[11];
    const float* b2   = (const float*)d_in[12];
    const float* g2   = (const float*)d_in[13];
    const float* be2  = (const float*)d_in[14];
    const float* W3   = (const float*)d_in[15];
    const float* b3   = (const float*)d_in[16];
    const float* slog = (const float*)d_in[17];

    const int Bn = in_sizes[0] / 7;
    const size_t smem = (size_t)SMEM_BYTES;

    cudaFuncSetAttribute(irm_kernel, cudaFuncAttributeMaxDynamicSharedMemorySize, (int)smem);

    const int grid = (Bn + EPB - 1) / EPB;
    irm_kernel<<<grid, TPB, smem>>>(ang, tgt, Kc, Re, te, vmk,
                                    W1, b1, g1, be1, W2, b2, g2, be2, W3, b3,
                                    slog, (float*)d_out, Bn);
}